// round 11
// baseline (speedup 1.0000x reference)
#include <cuda_runtime.h>
#include <cuda_fp16.h>
#include <cstdint>

#define BT 48
#define NN 1024
#define FF 64

// ---------------------------------------------------------------- helpers
__device__ __forceinline__ uint32_t smem_to_u32(const void* p) {
    uint32_t a;
    asm("{ .reg .u64 t; cvta.to.shared.u64 t, %1; cvt.u32.u64 %0, t; }" : "=r"(a) : "l"(p));
    return a;
}
__device__ __forceinline__ void ldsm_x4(uint32_t& r0, uint32_t& r1, uint32_t& r2, uint32_t& r3,
                                        uint32_t addr) {
    asm volatile("ldmatrix.sync.aligned.m8n8.x4.shared.b16 {%0,%1,%2,%3}, [%4];"
                 : "=r"(r0), "=r"(r1), "=r"(r2), "=r"(r3) : "r"(addr));
}
__device__ __forceinline__ void mma_f16(float* c, uint32_t a0, uint32_t a1, uint32_t a2,
                                        uint32_t a3, uint32_t b0, uint32_t b1) {
    asm volatile(
        "mma.sync.aligned.m16n8k16.row.col.f32.f16.f16.f32 "
        "{%0,%1,%2,%3}, {%4,%5,%6,%7}, {%8,%9}, {%0,%1,%2,%3};"
        : "+f"(c[0]), "+f"(c[1]), "+f"(c[2]), "+f"(c[3])
        : "r"(a0), "r"(a1), "r"(a2), "r"(a3), "r"(b0), "r"(b1));
}
#define SWZ(off) ((off) ^ (((off) >> 3) & 0x70))

// ---------------------------------------------------------------- globals
__device__ __align__(16) __half g_B[BT * FF * NN];   // Wh^T fp16 (f-major, k=j)
__device__ __align__(16) __half g_EuH[BT * NN], g_FuH[BT * NN];  // scaled by 0.25
__device__ __align__(16) __half g_EvH[BT * NN], g_FvH[BT * NN];
__device__ unsigned g_adjbits[NN * NN / 32];

// ---------------------------------------------------------------- fused prep + pack
// blockIdx.y <  BT : Wh tile GEMM -> u,v -> exp factors -> fp16 B   (768 blocks)
// blockIdx.y >= BT : adjacency bit-pack, MLP=8                      (128 blocks)
__global__ void __launch_bounds__(256) k_prep(const float* __restrict__ x,
                                              const float* __restrict__ W,
                                              const float* __restrict__ a,
                                              const float* __restrict__ emb1,
                                              const float* __restrict__ emb2,
                                              const float* __restrict__ a2,
                                              const int* __restrict__ adj) {
    __shared__ __align__(16) float Ws[64 * 64];
    __shared__ __align__(16) float ts[64][68];
    __shared__ float sa[128];
    int tid = threadIdx.x;
    int bx = blockIdx.x, by = blockIdx.y;

    if (by >= BT) {
        // ---- pack path
        int pb = (by - BT) * 16 + bx;          // 0..127
        const uint4* a4 = (const uint4*)adj;
        int lane = tid & 31;
        unsigned grp = lane >> 3;
        unsigned msk = 0xFFu << (8 * grp);
        int gid0 = pb * 2048 + tid;
        uint4 v[8];
#pragma unroll
        for (int k = 0; k < 8; k++) v[k] = a4[gid0 + 256 * k];
#pragma unroll
        for (int k = 0; k < 8; k++) {
            unsigned nib = (v[k].x ? 1u : 0u) | (v[k].y ? 2u : 0u) |
                           (v[k].z ? 4u : 0u) | (v[k].w ? 8u : 0u);
            unsigned w = __reduce_or_sync(msk, nib << (4 * (lane & 7)));
            if ((lane & 7) == 0) g_adjbits[(gid0 + 256 * k) >> 3] = w;
        }
        return;
    }

    // ---- prep path
    int bt = by, j0 = bx * 64;

    const float4* W4 = (const float4*)W;
    float4* Ws4 = (float4*)Ws;
#pragma unroll
    for (int k = 0; k < 4; k++) Ws4[tid + 256 * k] = W4[tid + 256 * k];
    if (tid < 128) sa[tid] = a[tid];
#pragma unroll
    for (int kk = 0; kk < 4; kk++) {
        int idx = tid + 256 * kk;
        int r = idx >> 4, c = idx & 15;
        float4 v = *(const float4*)&x[((size_t)(bt * NN) + j0 + r) * 64 + c * 4];
        *(float4*)&ts[r][c * 4] = v;
    }
    __syncthreads();

    int f = tid & 63, rb = tid >> 6;
    float acc[16];
#pragma unroll
    for (int r = 0; r < 16; r++) acc[r] = 0.f;
    for (int k4 = 0; k4 < 16; k4++) {
        float w0 = Ws[(4 * k4 + 0) * 64 + f];
        float w1 = Ws[(4 * k4 + 1) * 64 + f];
        float w2 = Ws[(4 * k4 + 2) * 64 + f];
        float w3 = Ws[(4 * k4 + 3) * 64 + f];
#pragma unroll
        for (int r = 0; r < 16; r++) {
            float4 v = *(const float4*)&ts[rb + 4 * r][4 * k4];
            acc[r] += v.x * w0 + v.y * w1 + v.z * w2 + v.w * w3;
        }
    }
    __syncthreads();
#pragma unroll
    for (int r = 0; r < 16; r++) ts[rb + 4 * r][f] = acc[r];
    __syncthreads();

    {
        int row = tid >> 2, fq = tid & 3;
        float u = 0.f, v = 0.f;
#pragma unroll
        for (int m = 0; m < 16; m++) {
            float wv = ts[row][fq * 16 + m];
            u += wv * sa[fq * 16 + m];
            v += wv * sa[64 + fq * 16 + m];
        }
#pragma unroll
        for (int m = 0; m < 4; m++) {
            u += emb1[(j0 + row) * 16 + fq * 4 + m] * a2[fq * 4 + m];
            v += emb2[(j0 + row) * 16 + fq * 4 + m] * a2[16 + fq * 4 + m];
        }
        u += __shfl_xor_sync(0xFFFFFFFFu, u, 1);
        u += __shfl_xor_sync(0xFFFFFFFFu, u, 2);
        v += __shfl_xor_sync(0xFFFFFFFFu, v, 1);
        v += __shfl_xor_sync(0xFFFFFFFFu, v, 2);
        if (fq == 0) {
            int g = bt * NN + j0 + row;
            g_EuH[g] = __float2half_rn(__expf(u) * 0.25f);
            g_FuH[g] = __float2half_rn(__expf(0.2f * u) * 0.25f);
            g_EvH[g] = __float2half_rn(__expf(v));
            g_FvH[g] = __float2half_rn(__expf(0.2f * v));
        }
    }

#pragma unroll
    for (int kk = 0; kk < 8; kk++) {
        int pi = tid + 256 * kk;
        int ff = pi >> 5, jp = pi & 31;
        float x0 = ts[2 * jp][ff], x1 = ts[2 * jp + 1][ff];
        size_t off = ((size_t)(bt * 64 + ff)) * NN + j0 + 2 * jp;
        *(__half2*)&g_B[off] = __floats2half2_rn(x0, x1);
    }
}

// ---------------------------------------------------------------- main attention kernel
// M=64 rows per CTA; warp tile 16M x 32N; 4 CTAs/SM. Double-buffered.
// MMA count = algorithmic floor (no accS); row sums via fp32 adds in build (FMA pipe idle).
static constexpr int OFF_A = 0;          // 8192
static constexpr int OFF_B = 8192;       // 8192
static constexpr int BUFSZ = 16384;
static constexpr int OFF_ADJ = 32768;    // 8192
static constexpr int OFF_EV = 40960;     // 2048
static constexpr int OFF_FV = 43008;     // 2048
static constexpr int OFF_EU = 45056;     // 128
static constexpr int OFF_FU = 45184;     // 128
static constexpr int OFF_LUT = 45312;    // 128
static constexpr int OFF_SUM = 45440;    // 256
static constexpr int SMEM_DYN = 45696;   // x4 CTAs = 182784 <= 228KB

__global__ void __launch_bounds__(256, 4) k_att(float* __restrict__ out) {
    extern __shared__ char sm[];
    const uint32_t sb = smem_to_u32(sm);

    const int tid = threadIdx.x;
    const int wid = tid >> 5, lane = tid & 31;
    const int bt = blockIdx.y;
    const int i0 = blockIdx.x * 64;

    __half* sEvH = (__half*)(sm + OFF_EV);
    __half* sFvH = (__half*)(sm + OFF_FV);
    __half* sEuH = (__half*)(sm + OFF_EU);
    __half* sFuH = (__half*)(sm + OFF_FU);
    unsigned* sAdj = (unsigned*)(sm + OFF_ADJ);
    uint2* sLut = (uint2*)(sm + OFF_LUT);
    float* sSum = (float*)(sm + OFF_SUM);

    if (tid < 128) {
        ((uint4*)sEvH)[tid] = ((const uint4*)(g_EvH + bt * NN))[tid];
        ((uint4*)sFvH)[tid] = ((const uint4*)(g_FvH + bt * NN))[tid];
    } else if (tid < 136) {
        ((uint4*)sEuH)[tid - 128] = ((const uint4*)(g_EuH + bt * NN + i0))[tid - 128];
        ((uint4*)sFuH)[tid - 128] = ((const uint4*)(g_FuH + bt * NN + i0))[tid - 128];
    } else if (tid >= 144 && tid < 160) {
        int n = tid - 144;
        uint2 m;
        m.x = ((n & 1) ? 0xFFFFu : 0u) | ((n & 2) ? 0xFFFF0000u : 0u);
        m.y = ((n & 4) ? 0xFFFFu : 0u) | ((n & 8) ? 0xFFFF0000u : 0u);
        sLut[n] = m;
    }
    {
        const uint4* gv = (const uint4*)(g_adjbits + (size_t)i0 * 32);
        uint4* sv4 = (uint4*)sAdj;
#pragma unroll
        for (int k = 0; k < 2; k++) sv4[tid + 256 * k] = gv[tid + 256 * k];
    }
    __syncthreads();

    // p-build thread mapping: 64x64 tile, 16 elems/thread
    const int jq = tid & 15;
    const int rb = tid >> 4;
    const int wcolq = jq >> 3;
    const int sh = (jq * 4) & 31;
    __half2 Eu2[4], Fu2[4];
#pragma unroll
    for (int k = 0; k < 4; k++) {
        Eu2[k] = __half2half2(sEuH[rb + 16 * k]);
        Fu2[k] = __half2half2(sFuH[rb + 16 * k]);
    }

    // ldmatrix addressing: warp tile 16M x 32N
    const int mg = wid >> 1;
    const int ngrp = wid & 1;
    const int arow0 = 16 * mg + (lane & 15);
    const uint32_t aBase0 = (uint32_t)arow0 * 128 + ((lane >> 4) << 4);
    const uint32_t aXor = (uint32_t)(arow0 & 7) << 4;
    const int brl = (lane & 7) | ((lane & 16) >> 1);
    const uint32_t bKoff = (uint32_t)(lane & 8) << 1;
    const uint32_t brow0 = 32 * ngrp + brl;
    const uint32_t bXor = (brow0 & 7) << 4;

    float acc[4][4];
#pragma unroll
    for (int g = 0; g < 4; g++)
#pragma unroll
        for (int c = 0; c < 4; c++) acc[g][c] = 0.f;
    float rsum[4];
#pragma unroll
    for (int k = 0; k < 4; k++) rsum[k] = 0.f;

#define STAGE_B(T, BASE)                                                                   \
    do {                                                                                   \
        const int _j0 = (T) * 64;                                                          \
        _Pragma("unroll") for (int rr = 0; rr < 2; rr++) {                                 \
            int idx = tid + 256 * rr;                                                      \
            int ff = idx >> 3, q = idx & 7;                                                \
            uint32_t so = SWZ((uint32_t)(ff * 128 + q * 16));                              \
            const uint4* srcb = (const uint4*)(g_B + ((size_t)(bt * 64 + ff)) * NN + _j0); \
            *(uint4*)(sm + (BASE) + OFF_B + so) = srcb[q];                                 \
        }                                                                                  \
    } while (0)

#define BUILD_A(T, BASE)                                                              \
    do {                                                                              \
        const int _j0 = (T) * 64;                                                     \
        __half2 ev0 = *(const __half2*)(sEvH + _j0 + jq * 4);                         \
        __half2 ev1 = *(const __half2*)(sEvH + _j0 + jq * 4 + 2);                     \
        __half2 fv0 = *(const __half2*)(sFvH + _j0 + jq * 4);                         \
        __half2 fv1 = *(const __half2*)(sFvH + _j0 + jq * 4 + 2);                     \
        const int wcol = (_j0 >> 5) + wcolq;                                          \
        _Pragma("unroll") for (int k = 0; k < 4; k++) {                               \
            int row = rb + 16 * k;                                                    \
            unsigned word = sAdj[row * 32 + wcol];                                    \
            uint2 msk = sLut[(word >> sh) & 15];                                      \
            __half2 p0 = __hmax2(__hmul2(Eu2[k], ev0), __hmul2(Fu2[k], fv0));         \
            __half2 p1 = __hmax2(__hmul2(Eu2[k], ev1), __hmul2(Fu2[k], fv1));         \
            uint2 hv;                                                                 \
            hv.x = *reinterpret_cast<uint32_t*>(&p0) & msk.x;                         \
            hv.y = *reinterpret_cast<uint32_t*>(&p1) & msk.y;                         \
            float2 f0 = __half22float2(*reinterpret_cast<__half2*>(&hv.x));           \
            float2 f1 = __half22float2(*reinterpret_cast<__half2*>(&hv.y));           \
            rsum[k] += (f0.x + f0.y) + (f1.x + f1.y);                                 \
            *(uint2*)(sm + (BASE) + OFF_A + SWZ((uint32_t)(row * 128 + jq * 8))) = hv;\
        }                                                                             \
    } while (0)

    // prologue
    STAGE_B(0, 0);
    BUILD_A(0, 0);
    __syncthreads();

    for (int t = 0; t < 16; t++) {
        const uint32_t baseCur = (uint32_t)(t & 1) * BUFSZ;
        const uint32_t baseNxt = (uint32_t)((t + 1) & 1) * BUFSZ;
        if (t < 15) {
            STAGE_B(t + 1, baseNxt);
            BUILD_A(t + 1, baseNxt);
        }
#pragma unroll
        for (int kk = 0; kk < 4; kk++) {
            uint32_t a0, a1, a2r, a3;
            uint32_t ao = (aBase0 + kk * 32) ^ aXor;
            ldsm_x4(a0, a1, a2r, a3, sb + baseCur + OFF_A + ao);
#pragma unroll
            for (int bg = 0; bg < 2; bg++) {
                uint32_t bo = ((brow0 + 16 * bg) * 128 + kk * 32 + bKoff) ^ bXor;
                uint32_t b0, b1, b2, b3;
                ldsm_x4(b0, b1, b2, b3, sb + baseCur + OFF_B + bo);
                mma_f16(acc[2 * bg + 0], a0, a1, a2r, a3, b0, b1);
                mma_f16(acc[2 * bg + 1], a0, a1, a2r, a3, b2, b3);
            }
        }
        __syncthreads();
    }

    // ---- row sums -> smem (reduce over the 16 jq lanes sharing each row)
#pragma unroll
    for (int k = 0; k < 4; k++) {
        float s = rsum[k];
        s += __shfl_xor_sync(0xFFFFFFFFu, s, 1);
        s += __shfl_xor_sync(0xFFFFFFFFu, s, 2);
        s += __shfl_xor_sync(0xFFFFFFFFu, s, 4);
        s += __shfl_xor_sync(0xFFFFFFFFu, s, 8);
        if (jq == 0) sSum[rb + 16 * k] = s;
    }
    __syncthreads();

    // ---- epilogue: normalize + ELU + store
    {
        int rloc = 16 * mg + (lane >> 2);
        float s0 = sSum[rloc], s1 = sSum[rloc + 8];
        float inv0 = (s0 > 0.f) ? (1.f / s0) : 0.f;
        float inv1 = (s1 > 0.f) ? (1.f / s1) : 0.f;
        float* op0 = out + ((size_t)(bt * NN + i0 + rloc)) * 64;
        float* op1 = op0 + (size_t)8 * 64;
#pragma unroll
        for (int bg = 0; bg < 2; bg++)
#pragma unroll
            for (int h = 0; h < 2; h++) {
                int colb = 32 * ngrp + 16 * bg + 8 * h + (lane & 3) * 2;
                const float* A = acc[2 * bg + h];
                float v0 = A[0] * inv0, v1 = A[1] * inv0;
                float v2 = A[2] * inv1, v3 = A[3] * inv1;
                float2 o0, o1;
                o0.x = (v0 > 0.f) ? v0 : (__expf(v0) - 1.f);
                o0.y = (v1 > 0.f) ? v1 : (__expf(v1) - 1.f);
                o1.x = (v2 > 0.f) ? v2 : (__expf(v2) - 1.f);
                o1.y = (v3 > 0.f) ? v3 : (__expf(v3) - 1.f);
                *(float2*)(op0 + colb) = o0;
                *(float2*)(op1 + colb) = o1;
            }
    }
}

// ---------------------------------------------------------------- launch
extern "C" void kernel_launch(void* const* d_in, const int* in_sizes, int n_in,
                              void* d_out, int out_size) {
    const float* x = (const float*)d_in[0];
    const int* adj = (const int*)d_in[1];
    const float* emb1 = (const float*)d_in[2];
    const float* emb2 = (const float*)d_in[3];
    const float* W = (const float*)d_in[4];
    const float* a = (const float*)d_in[5];
    const float* a2 = (const float*)d_in[6];
    float* out = (float*)d_out;

    static int smem_set = 0;
    if (!smem_set) {
        cudaFuncSetAttribute(k_att, cudaFuncAttributeMaxDynamicSharedMemorySize, SMEM_DYN);
        smem_set = 1;
    }

    dim3 gp(16, BT + 8);   // 768 prep blocks + 128 pack blocks, one launch
    k_prep<<<gp, 256>>>(x, W, a, emb1, emb2, a2, adj);
    dim3 ga(16, BT);
    k_att<<<ga, 256, SMEM_DYN>>>(out);
}

// round 12
// speedup vs baseline: 1.0786x; 1.0786x over previous
#include <cuda_runtime.h>
#include <cuda_fp16.h>
#include <cstdint>

#define BT 48
#define NN 1024
#define FF 64

// ---------------------------------------------------------------- helpers
__device__ __forceinline__ uint32_t smem_to_u32(const void* p) {
    uint32_t a;
    asm("{ .reg .u64 t; cvta.to.shared.u64 t, %1; cvt.u32.u64 %0, t; }" : "=r"(a) : "l"(p));
    return a;
}
__device__ __forceinline__ void ldsm_x4(uint32_t& r0, uint32_t& r1, uint32_t& r2, uint32_t& r3,
                                        uint32_t addr) {
    asm volatile("ldmatrix.sync.aligned.m8n8.x4.shared.b16 {%0,%1,%2,%3}, [%4];"
                 : "=r"(r0), "=r"(r1), "=r"(r2), "=r"(r3) : "r"(addr));
}
__device__ __forceinline__ void mma_f16(float* c, uint32_t a0, uint32_t a1, uint32_t a2,
                                        uint32_t a3, uint32_t b0, uint32_t b1) {
    asm volatile(
        "mma.sync.aligned.m16n8k16.row.col.f32.f16.f16.f32 "
        "{%0,%1,%2,%3}, {%4,%5,%6,%7}, {%8,%9}, {%0,%1,%2,%3};"
        : "+f"(c[0]), "+f"(c[1]), "+f"(c[2]), "+f"(c[3])
        : "r"(a0), "r"(a1), "r"(a2), "r"(a3), "r"(b0), "r"(b1));
}
#define SWZ(off) ((off) ^ (((off) >> 3) & 0x70))
#define ONE2 0x3C003C00u  // fp16 {1.0, 1.0}
#define CP_COMMIT() asm volatile("cp.async.commit_group;" ::: "memory")
#define CP_WAIT0() asm volatile("cp.async.wait_group 0;" ::: "memory")

// ---------------------------------------------------------------- globals
__device__ __align__(16) __half g_B[BT * FF * NN];   // Wh^T fp16 (f-major, k=j)
__device__ __align__(16) __half g_EuH[BT * NN], g_FuH[BT * NN];  // scaled by 0.25
__device__ __align__(16) __half g_EvH[BT * NN], g_FvH[BT * NN];
__device__ unsigned g_adjbits[NN * NN / 32];

// ---------------------------------------------------------------- prep kernels
__global__ void k_pack(const int* __restrict__ adj) {
    int gid = blockIdx.x * blockDim.x + threadIdx.x;
    int lane = threadIdx.x & 31;
    const uint4* a4 = (const uint4*)adj;
    uint4 va = a4[gid];
    uint4 vb = a4[gid + 131072];
    unsigned nibA = (va.x ? 1u : 0u) | (va.y ? 2u : 0u) | (va.z ? 4u : 0u) | (va.w ? 8u : 0u);
    unsigned nibB = (vb.x ? 1u : 0u) | (vb.y ? 2u : 0u) | (vb.z ? 4u : 0u) | (vb.w ? 8u : 0u);
    unsigned grp = lane >> 3;
    unsigned mask = 0xFFu << (8 * grp);
    unsigned wA = __reduce_or_sync(mask, nibA << (4 * (lane & 7)));
    unsigned wB = __reduce_or_sync(mask, nibB << (4 * (lane & 7)));
    if ((lane & 7) == 0) {
        g_adjbits[gid >> 3] = wA;
        g_adjbits[(gid + 131072) >> 3] = wB;
    }
}

// Fused: Wh tile GEMM -> u,v (+ emb terms) -> exp factors (fp16) -> fp16 B.
__global__ void __launch_bounds__(256) k_prep(const float* __restrict__ x,
                                              const float* __restrict__ W,
                                              const float* __restrict__ a,
                                              const float* __restrict__ emb1,
                                              const float* __restrict__ emb2,
                                              const float* __restrict__ a2) {
    __shared__ __align__(16) float Ws[64 * 64];
    __shared__ __align__(16) float ts[64][68];
    __shared__ float sa[128];
    int tid = threadIdx.x;
    int bt = blockIdx.y, j0 = blockIdx.x * 64;

    const float4* W4 = (const float4*)W;
    float4* Ws4 = (float4*)Ws;
#pragma unroll
    for (int k = 0; k < 4; k++) Ws4[tid + 256 * k] = W4[tid + 256 * k];
    if (tid < 128) sa[tid] = a[tid];
#pragma unroll
    for (int kk = 0; kk < 4; kk++) {
        int idx = tid + 256 * kk;
        int r = idx >> 4, c = idx & 15;
        float4 v = *(const float4*)&x[((size_t)(bt * NN) + j0 + r) * 64 + c * 4];
        *(float4*)&ts[r][c * 4] = v;
    }
    __syncthreads();

    int f = tid & 63, rb = tid >> 6;
    float acc[16];
#pragma unroll
    for (int r = 0; r < 16; r++) acc[r] = 0.f;
    for (int k4 = 0; k4 < 16; k4++) {
        float w0 = Ws[(4 * k4 + 0) * 64 + f];
        float w1 = Ws[(4 * k4 + 1) * 64 + f];
        float w2 = Ws[(4 * k4 + 2) * 64 + f];
        float w3 = Ws[(4 * k4 + 3) * 64 + f];
#pragma unroll
        for (int r = 0; r < 16; r++) {
            float4 v = *(const float4*)&ts[rb + 4 * r][4 * k4];
            acc[r] += v.x * w0 + v.y * w1 + v.z * w2 + v.w * w3;
        }
    }
    __syncthreads();
#pragma unroll
    for (int r = 0; r < 16; r++) ts[rb + 4 * r][f] = acc[r];
    __syncthreads();

    {
        int row = tid >> 2, fq = tid & 3;
        float u = 0.f, v = 0.f;
#pragma unroll
        for (int m = 0; m < 16; m++) {
            float wv = ts[row][fq * 16 + m];
            u += wv * sa[fq * 16 + m];
            v += wv * sa[64 + fq * 16 + m];
        }
#pragma unroll
        for (int m = 0; m < 4; m++) {
            u += emb1[(j0 + row) * 16 + fq * 4 + m] * a2[fq * 4 + m];
            v += emb2[(j0 + row) * 16 + fq * 4 + m] * a2[16 + fq * 4 + m];
        }
        u += __shfl_xor_sync(0xFFFFFFFFu, u, 1);
        u += __shfl_xor_sync(0xFFFFFFFFu, u, 2);
        v += __shfl_xor_sync(0xFFFFFFFFu, v, 1);
        v += __shfl_xor_sync(0xFFFFFFFFu, v, 2);
        if (fq == 0) {
            int g = bt * NN + j0 + row;
            g_EuH[g] = __float2half_rn(__expf(u) * 0.25f);
            g_FuH[g] = __float2half_rn(__expf(0.2f * u) * 0.25f);
            g_EvH[g] = __float2half_rn(__expf(v));
            g_FvH[g] = __float2half_rn(__expf(0.2f * v));
        }
    }

#pragma unroll
    for (int kk = 0; kk < 8; kk++) {
        int pi = tid + 256 * kk;
        int ff = pi >> 5, jp = pi & 31;
        float x0 = ts[2 * jp][ff], x1 = ts[2 * jp + 1][ff];
        size_t off = ((size_t)(bt * 64 + ff)) * NN + j0 + 2 * jp;
        *(__half2*)&g_B[off] = __floats2half2_rn(x0, x1);
    }
}

// ---------------------------------------------------------------- main attention kernel
// M=64/CTA, warp tile 16Mx32N, 4 CTAs/SM. B staged via cp.async one tile ahead.
// Row sums via accS MMA on ngrp==0 warps (tensor pipe has headroom).
static constexpr int OFF_A = 0;          // 8192
static constexpr int OFF_B = 8192;       // 8192
static constexpr int BUFSZ = 16384;
static constexpr int OFF_ADJ = 32768;    // 8192
static constexpr int OFF_EV = 40960;     // 2048
static constexpr int OFF_FV = 43008;     // 2048
static constexpr int OFF_EU = 45056;     // 128
static constexpr int OFF_FU = 45184;     // 128
static constexpr int OFF_LUT = 45312;    // 128
static constexpr int OFF_SUM = 45440;    // 256
static constexpr int SMEM_DYN = 45696;   // x4 CTAs = 182784 <= 228KB

__global__ void __launch_bounds__(256, 4) k_att(float* __restrict__ out) {
    extern __shared__ char sm[];
    const uint32_t sb = smem_to_u32(sm);

    const int tid = threadIdx.x;
    const int wid = tid >> 5, lane = tid & 31;
    const int bt = blockIdx.y;
    const int i0 = blockIdx.x * 64;

    __half* sEvH = (__half*)(sm + OFF_EV);
    __half* sFvH = (__half*)(sm + OFF_FV);
    __half* sEuH = (__half*)(sm + OFF_EU);
    __half* sFuH = (__half*)(sm + OFF_FU);
    unsigned* sAdj = (unsigned*)(sm + OFF_ADJ);
    uint2* sLut = (uint2*)(sm + OFF_LUT);
    float* sSum = (float*)(sm + OFF_SUM);

    if (tid < 128) {
        ((uint4*)sEvH)[tid] = ((const uint4*)(g_EvH + bt * NN))[tid];
        ((uint4*)sFvH)[tid] = ((const uint4*)(g_FvH + bt * NN))[tid];
    } else if (tid < 136) {
        ((uint4*)sEuH)[tid - 128] = ((const uint4*)(g_EuH + bt * NN + i0))[tid - 128];
        ((uint4*)sFuH)[tid - 128] = ((const uint4*)(g_FuH + bt * NN + i0))[tid - 128];
    } else if (tid >= 144 && tid < 160) {
        int n = tid - 144;
        uint2 m;
        m.x = ((n & 1) ? 0xFFFFu : 0u) | ((n & 2) ? 0xFFFF0000u : 0u);
        m.y = ((n & 4) ? 0xFFFFu : 0u) | ((n & 8) ? 0xFFFF0000u : 0u);
        sLut[n] = m;
    }
    {
        const uint4* gv = (const uint4*)(g_adjbits + (size_t)i0 * 32);
        uint4* sv4 = (uint4*)sAdj;
#pragma unroll
        for (int k = 0; k < 2; k++) sv4[tid + 256 * k] = gv[tid + 256 * k];
    }
    __syncthreads();

    // p-build thread mapping: 64x64 tile, 16 elems/thread
    const int jq = tid & 15;
    const int rb = tid >> 4;
    const int wcolq = jq >> 3;
    const int sh = (jq * 4) & 31;
    __half2 Eu2[4], Fu2[4];
#pragma unroll
    for (int k = 0; k < 4; k++) {
        Eu2[k] = __half2half2(sEuH[rb + 16 * k]);
        Fu2[k] = __half2half2(sFuH[rb + 16 * k]);
    }

    // ldmatrix addressing: warp tile 16M x 32N
    const int mg = wid >> 1;
    const int ngrp = wid & 1;
    const int arow0 = 16 * mg + (lane & 15);
    const uint32_t aBase0 = (uint32_t)arow0 * 128 + ((lane >> 4) << 4);
    const uint32_t aXor = (uint32_t)(arow0 & 7) << 4;
    const int brl = (lane & 7) | ((lane & 16) >> 1);
    const uint32_t bKoff = (uint32_t)(lane & 8) << 1;
    const uint32_t brow0 = 32 * ngrp + brl;
    const uint32_t bXor = (brow0 & 7) << 4;

    float acc[4][4];
#pragma unroll
    for (int g = 0; g < 4; g++)
#pragma unroll
        for (int c = 0; c < 4; c++) acc[g][c] = 0.f;
    float accS[4];
#pragma unroll
    for (int c = 0; c < 4; c++) accS[c] = 0.f;

#define STAGE_B_ASYNC(T, BASE)                                                        \
    do {                                                                              \
        const int _j0 = (T) * 64;                                                     \
        _Pragma("unroll") for (int rr = 0; rr < 2; rr++) {                            \
            int idx = tid + 256 * rr;                                                 \
            int ff = idx >> 3, q = idx & 7;                                           \
            uint32_t so = SWZ((uint32_t)(ff * 128 + q * 16));                         \
            const __half* src = g_B + ((size_t)(bt * 64 + ff)) * NN + _j0 + q * 8;    \
            asm volatile("cp.async.cg.shared.global [%0], [%1], 16;"                  \
                :: "r"(sb + (BASE) + OFF_B + so), "l"(src) : "memory");               \
        }                                                                             \
    } while (0)

#define BUILD_A(T, BASE)                                                              \
    do {                                                                              \
        const int _j0 = (T) * 64;                                                     \
        __half2 ev0 = *(const __half2*)(sEvH + _j0 + jq * 4);                         \
        __half2 ev1 = *(const __half2*)(sEvH + _j0 + jq * 4 + 2);                     \
        __half2 fv0 = *(const __half2*)(sFvH + _j0 + jq * 4);                         \
        __half2 fv1 = *(const __half2*)(sFvH + _j0 + jq * 4 + 2);                     \
        const int wcol = (_j0 >> 5) + wcolq;                                          \
        _Pragma("unroll") for (int k = 0; k < 4; k++) {                               \
            int row = rb + 16 * k;                                                    \
            unsigned word = sAdj[row * 32 + wcol];                                    \
            uint2 msk = sLut[(word >> sh) & 15];                                      \
            __half2 p0 = __hmax2(__hmul2(Eu2[k], ev0), __hmul2(Fu2[k], fv0));         \
            __half2 p1 = __hmax2(__hmul2(Eu2[k], ev1), __hmul2(Fu2[k], fv1));         \
            uint2 hv;                                                                 \
            hv.x = *reinterpret_cast<uint32_t*>(&p0) & msk.x;                         \
            hv.y = *reinterpret_cast<uint32_t*>(&p1) & msk.y;                         \
            *(uint2*)(sm + (BASE) + OFF_A + SWZ((uint32_t)(row * 128 + jq * 8))) = hv;\
        }                                                                             \
    } while (0)

    // prologue: async-stage B0, build A0, wait, sync
    STAGE_B_ASYNC(0, 0);
    CP_COMMIT();
    BUILD_A(0, 0);
    CP_WAIT0();
    __syncthreads();

    for (int t = 0; t < 16; t++) {
        const uint32_t baseCur = (uint32_t)(t & 1) * BUFSZ;
        const uint32_t baseNxt = (uint32_t)((t + 1) & 1) * BUFSZ;
        if (t < 15) {
            STAGE_B_ASYNC(t + 1, baseNxt);   // latency hidden by build + MMA below
            CP_COMMIT();
            BUILD_A(t + 1, baseNxt);
        }
#pragma unroll
        for (int kk = 0; kk < 4; kk++) {
            uint32_t a0, a1, a2r, a3;
            uint32_t ao = (aBase0 + kk * 32) ^ aXor;
            ldsm_x4(a0, a1, a2r, a3, sb + baseCur + OFF_A + ao);
            if (ngrp == 0) mma_f16(accS, a0, a1, a2r, a3, ONE2, ONE2);
#pragma unroll
            for (int bg = 0; bg < 2; bg++) {
                uint32_t bo = ((brow0 + 16 * bg) * 128 + kk * 32 + bKoff) ^ bXor;
                uint32_t b0, b1, b2, b3;
                ldsm_x4(b0, b1, b2, b3, sb + baseCur + OFF_B + bo);
                mma_f16(acc[2 * bg + 0], a0, a1, a2r, a3, b0, b1);
                mma_f16(acc[2 * bg + 1], a0, a1, a2r, a3, b2, b3);
            }
        }
        if (t < 15) CP_WAIT0();
        __syncthreads();
    }

    // ---- share row sums (ngrp==0 warps own them)
    if (ngrp == 0) {
        int r = 16 * mg + (lane >> 2);
        sSum[r] = accS[0];
        sSum[r + 8] = accS[2];
    }
    __syncthreads();

    // ---- epilogue: normalize + ELU + store
    {
        int rloc = 16 * mg + (lane >> 2);
        float s0 = sSum[rloc], s1 = sSum[rloc + 8];
        float inv0 = (s0 > 0.f) ? (1.f / s0) : 0.f;
        float inv1 = (s1 > 0.f) ? (1.f / s1) : 0.f;
        float* op0 = out + ((size_t)(bt * NN + i0 + rloc)) * 64;
        float* op1 = op0 + (size_t)8 * 64;
#pragma unroll
        for (int bg = 0; bg < 2; bg++)
#pragma unroll
            for (int h = 0; h < 2; h++) {
                int colb = 32 * ngrp + 16 * bg + 8 * h + (lane & 3) * 2;
                const float* A = acc[2 * bg + h];
                float v0 = A[0] * inv0, v1 = A[1] * inv0;
                float v2 = A[2] * inv1, v3 = A[3] * inv1;
                float2 o0, o1;
                o0.x = (v0 > 0.f) ? v0 : (__expf(v0) - 1.f);
                o0.y = (v1 > 0.f) ? v1 : (__expf(v1) - 1.f);
                o1.x = (v2 > 0.f) ? v2 : (__expf(v2) - 1.f);
                o1.y = (v3 > 0.f) ? v3 : (__expf(v3) - 1.f);
                *(float2*)(op0 + colb) = o0;
                *(float2*)(op1 + colb) = o1;
            }
    }
}

// ---------------------------------------------------------------- launch
extern "C" void kernel_launch(void* const* d_in, const int* in_sizes, int n_in,
                              void* d_out, int out_size) {
    const float* x = (const float*)d_in[0];
    const int* adj = (const int*)d_in[1];
    const float* emb1 = (const float*)d_in[2];
    const float* emb2 = (const float*)d_in[3];
    const float* W = (const float*)d_in[4];
    const float* a = (const float*)d_in[5];
    const float* a2 = (const float*)d_in[6];
    float* out = (float*)d_out;

    static int smem_set = 0;
    if (!smem_set) {
        cudaFuncSetAttribute(k_att, cudaFuncAttributeMaxDynamicSharedMemorySize, SMEM_DYN);
        smem_set = 1;
    }

    k_pack<<<512, 256>>>(adj);
    dim3 gp(16, BT);
    k_prep<<<gp, 256>>>(x, W, a, emb1, emb2, a2);
    dim3 ga(16, BT);
    k_att<<<ga, 256, SMEM_DYN>>>(out);
}

// round 13
// speedup vs baseline: 1.1240x; 1.0421x over previous
#include <cuda_runtime.h>
#include <cuda_fp16.h>
#include <cstdint>

#define BT 48
#define NN 1024
#define FF 64

// ---------------------------------------------------------------- helpers
__device__ __forceinline__ uint32_t smem_to_u32(const void* p) {
    uint32_t a;
    asm("{ .reg .u64 t; cvta.to.shared.u64 t, %1; cvt.u32.u64 %0, t; }" : "=r"(a) : "l"(p));
    return a;
}
__device__ __forceinline__ void ldsm_x4(uint32_t& r0, uint32_t& r1, uint32_t& r2, uint32_t& r3,
                                        uint32_t addr) {
    asm volatile("ldmatrix.sync.aligned.m8n8.x4.shared.b16 {%0,%1,%2,%3}, [%4];"
                 : "=r"(r0), "=r"(r1), "=r"(r2), "=r"(r3) : "r"(addr));
}
__device__ __forceinline__ void mma_f16(float* c, uint32_t a0, uint32_t a1, uint32_t a2,
                                        uint32_t a3, uint32_t b0, uint32_t b1) {
    asm volatile(
        "mma.sync.aligned.m16n8k16.row.col.f32.f16.f16.f32 "
        "{%0,%1,%2,%3}, {%4,%5,%6,%7}, {%8,%9}, {%0,%1,%2,%3};"
        : "+f"(c[0]), "+f"(c[1]), "+f"(c[2]), "+f"(c[3])
        : "r"(a0), "r"(a1), "r"(a2), "r"(a3), "r"(b0), "r"(b1));
}
#define SWZ(off) ((off) ^ (((off) >> 3) & 0x70))
#define ONE2 0x3C003C00u  // fp16 {1.0, 1.0}
#define CP_COMMIT() asm volatile("cp.async.commit_group;" ::: "memory")
#define CP_WAIT0() asm volatile("cp.async.wait_group 0;" ::: "memory")

// ---------------------------------------------------------------- globals
__device__ __align__(16) __half g_B[BT * FF * NN];   // Wh^T fp16 (f-major, k=j)
__device__ __align__(16) __half g_EuH[BT * NN], g_FuH[BT * NN];  // scaled by 0.25
__device__ __align__(16) __half g_EvH[BT * NN], g_FvH[BT * NN];
__device__ unsigned g_adjbits[NN * NN / 32];

// ---------------------------------------------------------------- prep kernels
// MLP=4: each thread loads 4 uint4, hoisted.
__global__ void k_pack(const int* __restrict__ adj) {
    int gid = blockIdx.x * blockDim.x + threadIdx.x;     // 65536 threads
    int lane = threadIdx.x & 31;
    const uint4* a4 = (const uint4*)adj;
    uint4 v[4];
#pragma unroll
    for (int k = 0; k < 4; k++) v[k] = a4[gid + 65536 * k];
    unsigned grp = lane >> 3;
    unsigned mask = 0xFFu << (8 * grp);
#pragma unroll
    for (int k = 0; k < 4; k++) {
        unsigned nib = (v[k].x ? 1u : 0u) | (v[k].y ? 2u : 0u) |
                       (v[k].z ? 4u : 0u) | (v[k].w ? 8u : 0u);
        unsigned w = __reduce_or_sync(mask, nib << (4 * (lane & 7)));
        if ((lane & 7) == 0) g_adjbits[(gid + 65536 * k) >> 3] = w;
    }
}

// Fused: Wh tile GEMM -> u,v (+ emb terms) -> exp factors (fp16) -> fp16 B.
__global__ void __launch_bounds__(256) k_prep(const float* __restrict__ x,
                                              const float* __restrict__ W,
                                              const float* __restrict__ a,
                                              const float* __restrict__ emb1,
                                              const float* __restrict__ emb2,
                                              const float* __restrict__ a2) {
    __shared__ __align__(16) float Ws[64 * 64];
    __shared__ __align__(16) float ts[64][68];
    __shared__ float sa[128];
    int tid = threadIdx.x;
    int bt = blockIdx.y, j0 = blockIdx.x * 64;

    const float4* W4 = (const float4*)W;
    float4* Ws4 = (float4*)Ws;
#pragma unroll
    for (int k = 0; k < 4; k++) Ws4[tid + 256 * k] = W4[tid + 256 * k];
    if (tid < 128) sa[tid] = a[tid];
#pragma unroll
    for (int kk = 0; kk < 4; kk++) {
        int idx = tid + 256 * kk;
        int r = idx >> 4, c = idx & 15;
        float4 v = *(const float4*)&x[((size_t)(bt * NN) + j0 + r) * 64 + c * 4];
        *(float4*)&ts[r][c * 4] = v;
    }
    __syncthreads();

    int f = tid & 63, rb = tid >> 6;
    float acc[16];
#pragma unroll
    for (int r = 0; r < 16; r++) acc[r] = 0.f;
    for (int k4 = 0; k4 < 16; k4++) {
        float w0 = Ws[(4 * k4 + 0) * 64 + f];
        float w1 = Ws[(4 * k4 + 1) * 64 + f];
        float w2 = Ws[(4 * k4 + 2) * 64 + f];
        float w3 = Ws[(4 * k4 + 3) * 64 + f];
#pragma unroll
        for (int r = 0; r < 16; r++) {
            float4 v = *(const float4*)&ts[rb + 4 * r][4 * k4];
            acc[r] += v.x * w0 + v.y * w1 + v.z * w2 + v.w * w3;
        }
    }
    __syncthreads();
#pragma unroll
    for (int r = 0; r < 16; r++) ts[rb + 4 * r][f] = acc[r];
    __syncthreads();

    {
        int row = tid >> 2, fq = tid & 3;
        float u = 0.f, v = 0.f;
#pragma unroll
        for (int m = 0; m < 16; m++) {
            float wv = ts[row][fq * 16 + m];
            u += wv * sa[fq * 16 + m];
            v += wv * sa[64 + fq * 16 + m];
        }
#pragma unroll
        for (int m = 0; m < 4; m++) {
            u += emb1[(j0 + row) * 16 + fq * 4 + m] * a2[fq * 4 + m];
            v += emb2[(j0 + row) * 16 + fq * 4 + m] * a2[16 + fq * 4 + m];
        }
        u += __shfl_xor_sync(0xFFFFFFFFu, u, 1);
        u += __shfl_xor_sync(0xFFFFFFFFu, u, 2);
        v += __shfl_xor_sync(0xFFFFFFFFu, v, 1);
        v += __shfl_xor_sync(0xFFFFFFFFu, v, 2);
        if (fq == 0) {
            int g = bt * NN + j0 + row;
            g_EuH[g] = __float2half_rn(__expf(u) * 0.25f);
            g_FuH[g] = __float2half_rn(__expf(0.2f * u) * 0.25f);
            g_EvH[g] = __float2half_rn(__expf(v));
            g_FvH[g] = __float2half_rn(__expf(0.2f * v));
        }
    }

#pragma unroll
    for (int kk = 0; kk < 8; kk++) {
        int pi = tid + 256 * kk;
        int ff = pi >> 5, jp = pi & 31;
        float x0 = ts[2 * jp][ff], x1 = ts[2 * jp + 1][ff];
        size_t off = ((size_t)(bt * 64 + ff)) * NN + j0 + 2 * jp;
        *(__half2*)&g_B[off] = __floats2half2_rn(x0, x1);
    }
}

// ---------------------------------------------------------------- main attention kernel
// M=32 rows/CTA, 128 threads (4 warps, warp tile 16Mx32N), 7 CTAs/SM.
// Double-buffered; B via cp.async; row sums via accS MMA on ngrp==0 warps.
static constexpr int OFF_A = 0;          // 32*128 = 4096
static constexpr int OFF_B = 4096;       // 8192
static constexpr int BUFSZ = 12288;
static constexpr int OFF_ADJ = 24576;    // 32 rows * 128B = 4096
static constexpr int OFF_EV = 28672;     // 2048
static constexpr int OFF_FV = 30720;     // 2048
static constexpr int OFF_EU = 32768;     // 64
static constexpr int OFF_FU = 32832;     // 64
static constexpr int OFF_LUT = 32896;    // 128
static constexpr int OFF_SUM = 33024;    // 128
static constexpr int SMEM_DYN = 33152;   // x7 CTAs = 232064

__global__ void __launch_bounds__(128, 7) k_att(float* __restrict__ out) {
    extern __shared__ char sm[];
    const uint32_t sb = smem_to_u32(sm);

    const int tid = threadIdx.x;
    const int wid = tid >> 5, lane = tid & 31;
    const int bt = blockIdx.y;
    const int i0 = blockIdx.x * 32;

    __half* sEvH = (__half*)(sm + OFF_EV);
    __half* sFvH = (__half*)(sm + OFF_FV);
    __half* sEuH = (__half*)(sm + OFF_EU);
    __half* sFuH = (__half*)(sm + OFF_FU);
    unsigned* sAdj = (unsigned*)(sm + OFF_ADJ);
    uint2* sLut = (uint2*)(sm + OFF_LUT);
    float* sSum = (float*)(sm + OFF_SUM);

    // stage Ev/Fv (all 128 threads), Eu/Fu (8 uint4), LUT, adj (2 uint4/thread)
    ((uint4*)sEvH)[tid] = ((const uint4*)(g_EvH + bt * NN))[tid];
    ((uint4*)sFvH)[tid] = ((const uint4*)(g_FvH + bt * NN))[tid];
    if (tid < 4) {
        ((uint4*)sEuH)[tid] = ((const uint4*)(g_EuH + bt * NN + i0))[tid];
        ((uint4*)sFuH)[tid] = ((const uint4*)(g_FuH + bt * NN + i0))[tid];
    } else if (tid >= 16 && tid < 32) {
        int n = tid - 16;
        uint2 m;
        m.x = ((n & 1) ? 0xFFFFu : 0u) | ((n & 2) ? 0xFFFF0000u : 0u);
        m.y = ((n & 4) ? 0xFFFFu : 0u) | ((n & 8) ? 0xFFFF0000u : 0u);
        sLut[n] = m;
    }
    {
        const uint4* gv = (const uint4*)(g_adjbits + (size_t)i0 * 32);
        uint4* sv4 = (uint4*)sAdj;
#pragma unroll
        for (int k = 0; k < 2; k++) sv4[tid + 128 * k] = gv[tid + 128 * k];
    }
    __syncthreads();

    // p-build mapping: 32x64 tile, 16 elems/thread (rows rb+8k, k<4; j-quad jq)
    const int jq = tid & 15;
    const int rb = tid >> 4;          // 0..7
    const int wcolq = jq >> 3;
    const int sh = (jq * 4) & 31;
    __half2 Eu2[4], Fu2[4];
#pragma unroll
    for (int k = 0; k < 4; k++) {
        Eu2[k] = __half2half2(sEuH[rb + 8 * k]);
        Fu2[k] = __half2half2(sFuH[rb + 8 * k]);
    }

    // ldmatrix addressing: warp tile 16M x 32N (mg 0..1, ngrp 0..1)
    const int mg = wid >> 1;
    const int ngrp = wid & 1;
    const int arow0 = 16 * mg + (lane & 15);
    const uint32_t aBase0 = (uint32_t)arow0 * 128 + ((lane >> 4) << 4);
    const uint32_t aXor = (uint32_t)(arow0 & 7) << 4;
    const int brl = (lane & 7) | ((lane & 16) >> 1);
    const uint32_t bKoff = (uint32_t)(lane & 8) << 1;
    const uint32_t brow0 = 32 * ngrp + brl;
    const uint32_t bXor = (brow0 & 7) << 4;

    float acc[4][4];
#pragma unroll
    for (int g = 0; g < 4; g++)
#pragma unroll
        for (int c = 0; c < 4; c++) acc[g][c] = 0.f;
    float accS[4];
#pragma unroll
    for (int c = 0; c < 4; c++) accS[c] = 0.f;

#define STAGE_B_ASYNC(T, BASE)                                                        \
    do {                                                                              \
        const int _j0 = (T) * 64;                                                     \
        _Pragma("unroll") for (int rr = 0; rr < 4; rr++) {                            \
            int idx = tid + 128 * rr;                                                 \
            int ff = idx >> 3, q = idx & 7;                                           \
            uint32_t so = SWZ((uint32_t)(ff * 128 + q * 16));                         \
            const __half* src = g_B + ((size_t)(bt * 64 + ff)) * NN + _j0 + q * 8;    \
            asm volatile("cp.async.cg.shared.global [%0], [%1], 16;"                  \
                :: "r"(sb + (BASE) + OFF_B + so), "l"(src) : "memory");               \
        }                                                                             \
    } while (0)

#define BUILD_A(T, BASE)                                                              \
    do {                                                                              \
        const int _j0 = (T) * 64;                                                     \
        __half2 ev0 = *(const __half2*)(sEvH + _j0 + jq * 4);                         \
        __half2 ev1 = *(const __half2*)(sEvH + _j0 + jq * 4 + 2);                     \
        __half2 fv0 = *(const __half2*)(sFvH + _j0 + jq * 4);                         \
        __half2 fv1 = *(const __half2*)(sFvH + _j0 + jq * 4 + 2);                     \
        const int wcol = (_j0 >> 5) + wcolq;                                          \
        _Pragma("unroll") for (int k = 0; k < 4; k++) {                               \
            int row = rb + 8 * k;                                                     \
            unsigned word = sAdj[row * 32 + wcol];                                    \
            uint2 msk = sLut[(word >> sh) & 15];                                      \
            __half2 p0 = __hmax2(__hmul2(Eu2[k], ev0), __hmul2(Fu2[k], fv0));         \
            __half2 p1 = __hmax2(__hmul2(Eu2[k], ev1), __hmul2(Fu2[k], fv1));         \
            uint2 hv;                                                                 \
            hv.x = *reinterpret_cast<uint32_t*>(&p0) & msk.x;                         \
            hv.y = *reinterpret_cast<uint32_t*>(&p1) & msk.y;                         \
            *(uint2*)(sm + (BASE) + OFF_A + SWZ((uint32_t)(row * 128 + jq * 8))) = hv;\
        }                                                                             \
    } while (0)

    // prologue
    STAGE_B_ASYNC(0, 0);
    CP_COMMIT();
    BUILD_A(0, 0);
    CP_WAIT0();
    __syncthreads();

    for (int t = 0; t < 16; t++) {
        const uint32_t baseCur = (uint32_t)(t & 1) * BUFSZ;
        const uint32_t baseNxt = (uint32_t)((t + 1) & 1) * BUFSZ;
        if (t < 15) {
            STAGE_B_ASYNC(t + 1, baseNxt);
            CP_COMMIT();
            BUILD_A(t + 1, baseNxt);
        }
#pragma unroll
        for (int kk = 0; kk < 4; kk++) {
            uint32_t a0, a1, a2r, a3;
            uint32_t ao = (aBase0 + kk * 32) ^ aXor;
            ldsm_x4(a0, a1, a2r, a3, sb + baseCur + OFF_A + ao);
            if (ngrp == 0) mma_f16(accS, a0, a1, a2r, a3, ONE2, ONE2);
#pragma unroll
            for (int bg = 0; bg < 2; bg++) {
                uint32_t bo = ((brow0 + 16 * bg) * 128 + kk * 32 + bKoff) ^ bXor;
                uint32_t b0, b1, b2, b3;
                ldsm_x4(b0, b1, b2, b3, sb + baseCur + OFF_B + bo);
                mma_f16(acc[2 * bg + 0], a0, a1, a2r, a3, b0, b1);
                mma_f16(acc[2 * bg + 1], a0, a1, a2r, a3, b2, b3);
            }
        }
        if (t < 15) CP_WAIT0();
        __syncthreads();
    }

    // ---- share row sums (ngrp==0 warps own rows 16mg..16mg+15)
    if (ngrp == 0) {
        int r = 16 * mg + (lane >> 2);
        sSum[r] = accS[0];
        sSum[r + 8] = accS[2];
    }
    __syncthreads();

    // ---- epilogue: normalize + ELU + store
    {
        int rloc = 16 * mg + (lane >> 2);
        float s0 = sSum[rloc], s1 = sSum[rloc + 8];
        float inv0 = (s0 > 0.f) ? (1.f / s0) : 0.f;
        float inv1 = (s1 > 0.f) ? (1.f / s1) : 0.f;
        float* op0 = out + ((size_t)(bt * NN + i0 + rloc)) * 64;
        float* op1 = op0 + (size_t)8 * 64;
#pragma unroll
        for (int bg = 0; bg < 2; bg++)
#pragma unroll
            for (int h = 0; h < 2; h++) {
                int colb = 32 * ngrp + 16 * bg + 8 * h + (lane & 3) * 2;
                const float* A = acc[2 * bg + h];
                float v0 = A[0] * inv0, v1 = A[1] * inv0;
                float v2 = A[2] * inv1, v3 = A[3] * inv1;
                float2 o0, o1;
                o0.x = (v0 > 0.f) ? v0 : (__expf(v0) - 1.f);
                o0.y = (v1 > 0.f) ? v1 : (__expf(v1) - 1.f);
                o1.x = (v2 > 0.f) ? v2 : (__expf(v2) - 1.f);
                o1.y = (v3 > 0.f) ? v3 : (__expf(v3) - 1.f);
                *(float2*)(op0 + colb) = o0;
                *(float2*)(op1 + colb) = o1;
            }
    }
}

// ---------------------------------------------------------------- launch
extern "C" void kernel_launch(void* const* d_in, const int* in_sizes, int n_in,
                              void* d_out, int out_size) {
    const float* x = (const float*)d_in[0];
    const int* adj = (const int*)d_in[1];
    const float* emb1 = (const float*)d_in[2];
    const float* emb2 = (const float*)d_in[3];
    const float* W = (const float*)d_in[4];
    const float* a = (const float*)d_in[5];
    const float* a2 = (const float*)d_in[6];
    float* out = (float*)d_out;

    static int smem_set = 0;
    if (!smem_set) {
        cudaFuncSetAttribute(k_att, cudaFuncAttributeMaxDynamicSharedMemorySize, SMEM_DYN);
        smem_set = 1;
    }

    k_pack<<<256, 256>>>(adj);
    dim3 gp(16, BT);
    k_prep<<<gp, 256>>>(x, W, a, emb1, emb2, a2);
    dim3 ga(32, BT);
    k_att<<<ga, 128, SMEM_DYN>>>(out);
}

// round 14
// speedup vs baseline: 1.3500x; 1.2011x over previous
#include <cuda_runtime.h>
#include <cuda_fp16.h>
#include <cstdint>

#define BT 48
#define NN 1024
#define FF 64

// ---------------------------------------------------------------- helpers
__device__ __forceinline__ uint32_t smem_to_u32(const void* p) {
    uint32_t a;
    asm("{ .reg .u64 t; cvta.to.shared.u64 t, %1; cvt.u32.u64 %0, t; }" : "=r"(a) : "l"(p));
    return a;
}
__device__ __forceinline__ void ldsm_x4(uint32_t& r0, uint32_t& r1, uint32_t& r2, uint32_t& r3,
                                        uint32_t addr) {
    asm volatile("ldmatrix.sync.aligned.m8n8.x4.shared.b16 {%0,%1,%2,%3}, [%4];"
                 : "=r"(r0), "=r"(r1), "=r"(r2), "=r"(r3) : "r"(addr));
}
__device__ __forceinline__ void mma_f16(float* c, uint32_t a0, uint32_t a1, uint32_t a2,
                                        uint32_t a3, uint32_t b0, uint32_t b1) {
    asm volatile(
        "mma.sync.aligned.m16n8k16.row.col.f32.f16.f16.f32 "
        "{%0,%1,%2,%3}, {%4,%5,%6,%7}, {%8,%9}, {%0,%1,%2,%3};"
        : "+f"(c[0]), "+f"(c[1]), "+f"(c[2]), "+f"(c[3])
        : "r"(a0), "r"(a1), "r"(a2), "r"(a3), "r"(b0), "r"(b1));
}
#define SWZ(off) ((off) ^ (((off) >> 3) & 0x70))
#define CP_COMMIT() asm volatile("cp.async.commit_group;" ::: "memory")
#define CP_WAIT0() asm volatile("cp.async.wait_group 0;" ::: "memory")

// ---------------------------------------------------------------- globals
__device__ __align__(16) __half g_B[BT * FF * NN];   // Wh^T fp16 (f-major, k=j)
__device__ __align__(16) __half g_Wt16[FF * FF];     // W^T fp16 [f][k]
__device__ __align__(16) __half g_EuH[BT * NN], g_FuH[BT * NN];  // scaled by 0.25
__device__ __align__(16) __half g_EvH[BT * NN], g_FvH[BT * NN];
__device__ unsigned g_adjbits[NN * NN / 32];

// ---------------------------------------------------------------- pack (+ W transpose)
__global__ void k_pack(const int* __restrict__ adj, const float* __restrict__ W) {
    int gid = blockIdx.x * blockDim.x + threadIdx.x;   // 262144 threads
    int lane = threadIdx.x & 31;
    uint4 v = ((const uint4*)adj)[gid];
    unsigned nib = (v.x ? 1u : 0u) | (v.y ? 2u : 0u) | (v.z ? 4u : 0u) | (v.w ? 8u : 0u);
    unsigned grp = lane >> 3;
    unsigned mask = 0xFFu << (8 * grp);
    unsigned word = __reduce_or_sync(mask, nib << (4 * (lane & 7)));
    if ((lane & 7) == 0) g_adjbits[gid >> 3] = word;
    if (blockIdx.x == 0) {
#pragma unroll
        for (int kk = 0; kk < 16; kk++) {
            int e = threadIdx.x + 256 * kk;          // 4096 elements
            int f = e >> 6, k = e & 63;
            g_Wt16[f * 64 + k] = __float2half_rn(W[k * 64 + f]);
        }
    }
}

// ---------------------------------------------------------------- prep: tensor-core Wh
// Block (j0, bt), 128 threads: Wh[64 j x 64 f] = x_fp16 @ Wt^T via mma.
__global__ void __launch_bounds__(128) k_prep(const float* __restrict__ x,
                                              const float* __restrict__ a,
                                              const float* __restrict__ emb1,
                                              const float* __restrict__ emb2,
                                              const float* __restrict__ a2) {
    __shared__ __align__(16) char tiles[16384];   // [0,8K)=x fp16 swz, [8K,16K)=Wt fp16 swz
    __shared__ __align__(16) float ts[64][68];
    __shared__ float sa[128];
    const int tid = threadIdx.x;
    const int wid = tid >> 5, lane = tid & 31;
    const int bt = blockIdx.y, j0 = blockIdx.x * 64;
    const uint32_t tb = smem_to_u32(tiles);

    sa[tid] = a[tid];
    // stage Wt fp16 swizzled
#pragma unroll
    for (int rr = 0; rr < 4; rr++) {
        int idx = tid + 128 * rr;
        int ff = idx >> 3, q = idx & 7;
        *(uint4*)(tiles + 8192 + SWZ((uint32_t)(ff * 128 + q * 16))) =
            *(const uint4*)(g_Wt16 + ff * 64 + q * 8);
    }
    // stage x -> fp16 swizzled
#pragma unroll
    for (int rr = 0; rr < 4; rr++) {
        int idx = tid + 128 * rr;
        int row = idx >> 3, q = idx & 7;
        const float4* xs = (const float4*)&x[((size_t)(bt * NN) + j0 + row) * 64 + q * 8];
        float4 v0 = xs[0], v1 = xs[1];
        __half2 h0 = __floats2half2_rn(v0.x, v0.y);
        __half2 h1 = __floats2half2_rn(v0.z, v0.w);
        __half2 h2 = __floats2half2_rn(v1.x, v1.y);
        __half2 h3 = __floats2half2_rn(v1.z, v1.w);
        uint4 u;
        u.x = *reinterpret_cast<uint32_t*>(&h0);
        u.y = *reinterpret_cast<uint32_t*>(&h1);
        u.z = *reinterpret_cast<uint32_t*>(&h2);
        u.w = *reinterpret_cast<uint32_t*>(&h3);
        *(uint4*)(tiles + SWZ((uint32_t)(row * 128 + q * 16))) = u;
    }
    __syncthreads();

    // warp w: rows 16w..16w+15, all 64 f
    {
        const int arow = 16 * wid + (lane & 15);
        const uint32_t aBase = (uint32_t)arow * 128 + ((lane >> 4) << 4);
        const uint32_t aXor = (uint32_t)(arow & 7) << 4;
        const int brl = (lane & 7) | ((lane & 16) >> 1);
        const uint32_t bKoff = (uint32_t)(lane & 8) << 1;
        const uint32_t bXor = (uint32_t)(brl & 7) << 4;
        float acc[8][4];
#pragma unroll
        for (int g = 0; g < 8; g++)
#pragma unroll
            for (int c = 0; c < 4; c++) acc[g][c] = 0.f;
#pragma unroll
        for (int kk = 0; kk < 4; kk++) {
            uint32_t a0, a1, a2r, a3;
            ldsm_x4(a0, a1, a2r, a3, tb + ((aBase + kk * 32) ^ aXor));
#pragma unroll
            for (int bg = 0; bg < 4; bg++) {
                uint32_t brow = 16 * bg + brl;
                uint32_t bo = (brow * 128 + kk * 32 + bKoff) ^ bXor;
                uint32_t b0, b1, b2, b3;
                ldsm_x4(b0, b1, b2, b3, tb + 8192 + bo);
                mma_f16(acc[2 * bg + 0], a0, a1, a2r, a3, b0, b1);
                mma_f16(acc[2 * bg + 1], a0, a1, a2r, a3, b2, b3);
            }
        }
        int r0 = 16 * wid + (lane >> 2);
#pragma unroll
        for (int g = 0; g < 8; g++) {
            int c = g * 8 + 2 * (lane & 3);
            *(float2*)&ts[r0][c] = make_float2(acc[g][0], acc[g][1]);
            *(float2*)&ts[r0 + 8][c] = make_float2(acc[g][2], acc[g][3]);
        }
    }
    __syncthreads();

    // u,v: 2 threads per row
    {
        int row = tid >> 1, hf = tid & 1;
        float u = 0.f, v = 0.f;
#pragma unroll
        for (int m = 0; m < 32; m++) {
            float wv = ts[row][hf * 32 + m];
            u += wv * sa[hf * 32 + m];
            v += wv * sa[64 + hf * 32 + m];
        }
#pragma unroll
        for (int m = 0; m < 8; m++) {
            u += emb1[(j0 + row) * 16 + hf * 8 + m] * a2[hf * 8 + m];
            v += emb2[(j0 + row) * 16 + hf * 8 + m] * a2[16 + hf * 8 + m];
        }
        u += __shfl_xor_sync(0xFFFFFFFFu, u, 1);
        v += __shfl_xor_sync(0xFFFFFFFFu, v, 1);
        if (hf == 0) {
            int g = bt * NN + j0 + row;
            g_EuH[g] = __float2half_rn(__expf(u) * 0.25f);
            g_FuH[g] = __float2half_rn(__expf(0.2f * u) * 0.25f);
            g_EvH[g] = __float2half_rn(__expf(v));
            g_FvH[g] = __float2half_rn(__expf(0.2f * v));
        }
    }

    // transposed fp16 write: B[bt][f][j] = Wh[j][f]
#pragma unroll
    for (int kk = 0; kk < 16; kk++) {
        int pi = tid + 128 * kk;
        int ff = pi >> 5, jp = pi & 31;
        *(__half2*)&g_B[(size_t)(bt * 64 + ff) * NN + j0 + 2 * jp] =
            __floats2half2_rn(ts[2 * jp][ff], ts[2 * jp + 1][ff]);
    }
}

// ---------------------------------------------------------------- main attention kernel
// M=32/CTA, 128 thr, warp tile 16Mx32N, 7 CTAs/SM. cp.async B; double-buffered.
// MMA = algorithmic floor (16/warp-tile). Row sums via fp32 adds in build.
static constexpr int OFF_A = 0;          // 4096
static constexpr int OFF_B = 4096;       // 8192
static constexpr int BUFSZ = 12288;
static constexpr int OFF_ADJ = 24576;    // 4096
static constexpr int OFF_EV = 28672;     // 2048
static constexpr int OFF_FV = 30720;     // 2048
static constexpr int OFF_EU = 32768;     // 64
static constexpr int OFF_FU = 32832;     // 64
static constexpr int OFF_LUT = 32896;    // 128
static constexpr int OFF_SUM = 33024;    // 128
static constexpr int SMEM_DYN = 33152;

__global__ void __launch_bounds__(128, 7) k_att(float* __restrict__ out) {
    extern __shared__ char sm[];
    const uint32_t sb = smem_to_u32(sm);

    const int tid = threadIdx.x;
    const int wid = tid >> 5, lane = tid & 31;
    const int bt = blockIdx.y;
    const int i0 = blockIdx.x * 32;

    __half* sEvH = (__half*)(sm + OFF_EV);
    __half* sFvH = (__half*)(sm + OFF_FV);
    __half* sEuH = (__half*)(sm + OFF_EU);
    __half* sFuH = (__half*)(sm + OFF_FU);
    unsigned* sAdj = (unsigned*)(sm + OFF_ADJ);
    uint2* sLut = (uint2*)(sm + OFF_LUT);
    float* sSum = (float*)(sm + OFF_SUM);

    ((uint4*)sEvH)[tid] = ((const uint4*)(g_EvH + bt * NN))[tid];
    ((uint4*)sFvH)[tid] = ((const uint4*)(g_FvH + bt * NN))[tid];
    if (tid < 4) {
        ((uint4*)sEuH)[tid] = ((const uint4*)(g_EuH + bt * NN + i0))[tid];
        ((uint4*)sFuH)[tid] = ((const uint4*)(g_FuH + bt * NN + i0))[tid];
    } else if (tid >= 16 && tid < 32) {
        int n = tid - 16;
        uint2 m;
        m.x = ((n & 1) ? 0xFFFFu : 0u) | ((n & 2) ? 0xFFFF0000u : 0u);
        m.y = ((n & 4) ? 0xFFFFu : 0u) | ((n & 8) ? 0xFFFF0000u : 0u);
        sLut[n] = m;
    }
    {
        const uint4* gv = (const uint4*)(g_adjbits + (size_t)i0 * 32);
        uint4* sv4 = (uint4*)sAdj;
#pragma unroll
        for (int k = 0; k < 2; k++) sv4[tid + 128 * k] = gv[tid + 128 * k];
    }
    __syncthreads();

    const int jq = tid & 15;
    const int rb = tid >> 4;          // 0..7
    const int wcolq = jq >> 3;
    const int sh = (jq * 4) & 31;
    __half2 Eu2[4], Fu2[4];
#pragma unroll
    for (int k = 0; k < 4; k++) {
        Eu2[k] = __half2half2(sEuH[rb + 8 * k]);
        Fu2[k] = __half2half2(sFuH[rb + 8 * k]);
    }

    const int mg = wid >> 1;
    const int ngrp = wid & 1;
    const int arow0 = 16 * mg + (lane & 15);
    const uint32_t aBase0 = (uint32_t)arow0 * 128 + ((lane >> 4) << 4);
    const uint32_t aXor = (uint32_t)(arow0 & 7) << 4;
    const int brl = (lane & 7) | ((lane & 16) >> 1);
    const uint32_t bKoff = (uint32_t)(lane & 8) << 1;
    const uint32_t brow0 = 32 * ngrp + brl;
    const uint32_t bXor = (brow0 & 7) << 4;

    float acc[4][4];
#pragma unroll
    for (int g = 0; g < 4; g++)
#pragma unroll
        for (int c = 0; c < 4; c++) acc[g][c] = 0.f;
    float rsum[4];
#pragma unroll
    for (int k = 0; k < 4; k++) rsum[k] = 0.f;

#define STAGE_B_ASYNC(T, BASE)                                                        \
    do {                                                                              \
        const int _j0 = (T) * 64;                                                     \
        _Pragma("unroll") for (int rr = 0; rr < 4; rr++) {                            \
            int idx = tid + 128 * rr;                                                 \
            int ff = idx >> 3, q = idx & 7;                                           \
            uint32_t so = SWZ((uint32_t)(ff * 128 + q * 16));                         \
            const __half* src = g_B + ((size_t)(bt * 64 + ff)) * NN + _j0 + q * 8;    \
            asm volatile("cp.async.cg.shared.global [%0], [%1], 16;"                  \
                :: "r"(sb + (BASE) + OFF_B + so), "l"(src) : "memory");               \
        }                                                                             \
    } while (0)

#define BUILD_A(T, BASE)                                                              \
    do {                                                                              \
        const int _j0 = (T) * 64;                                                     \
        __half2 ev0 = *(const __half2*)(sEvH + _j0 + jq * 4);                         \
        __half2 ev1 = *(const __half2*)(sEvH + _j0 + jq * 4 + 2);                     \
        __half2 fv0 = *(const __half2*)(sFvH + _j0 + jq * 4);                         \
        __half2 fv1 = *(const __half2*)(sFvH + _j0 + jq * 4 + 2);                     \
        const int wcol = (_j0 >> 5) + wcolq;                                          \
        _Pragma("unroll") for (int k = 0; k < 4; k++) {                               \
            int row = rb + 8 * k;                                                     \
            unsigned word = sAdj[row * 32 + wcol];                                    \
            uint2 msk = sLut[(word >> sh) & 15];                                      \
            __half2 p0 = __hmax2(__hmul2(Eu2[k], ev0), __hmul2(Fu2[k], fv0));         \
            __half2 p1 = __hmax2(__hmul2(Eu2[k], ev1), __hmul2(Fu2[k], fv1));         \
            uint2 hv;                                                                 \
            hv.x = *reinterpret_cast<uint32_t*>(&p0) & msk.x;                         \
            hv.y = *reinterpret_cast<uint32_t*>(&p1) & msk.y;                         \
            float2 f0 = __half22float2(*reinterpret_cast<__half2*>(&hv.x));           \
            float2 f1 = __half22float2(*reinterpret_cast<__half2*>(&hv.y));           \
            rsum[k] += (f0.x + f0.y) + (f1.x + f1.y);                                 \
            *(uint2*)(sm + (BASE) + OFF_A + SWZ((uint32_t)(row * 128 + jq * 8))) = hv;\
        }                                                                             \
    } while (0)

    STAGE_B_ASYNC(0, 0);
    CP_COMMIT();
    BUILD_A(0, 0);
    CP_WAIT0();
    __syncthreads();

    for (int t = 0; t < 16; t++) {
        const uint32_t baseCur = (uint32_t)(t & 1) * BUFSZ;
        const uint32_t baseNxt = (uint32_t)((t + 1) & 1) * BUFSZ;
        if (t < 15) {
            STAGE_B_ASYNC(t + 1, baseNxt);
            CP_COMMIT();
            BUILD_A(t + 1, baseNxt);
        }
#pragma unroll
        for (int kk = 0; kk < 4; kk++) {
            uint32_t a0, a1, a2r, a3;
            uint32_t ao = (aBase0 + kk * 32) ^ aXor;
            ldsm_x4(a0, a1, a2r, a3, sb + baseCur + OFF_A + ao);
#pragma unroll
            for (int bg = 0; bg < 2; bg++) {
                uint32_t bo = ((brow0 + 16 * bg) * 128 + kk * 32 + bKoff) ^ bXor;
                uint32_t b0, b1, b2, b3;
                ldsm_x4(b0, b1, b2, b3, sb + baseCur + OFF_B + bo);
                mma_f16(acc[2 * bg + 0], a0, a1, a2r, a3, b0, b1);
                mma_f16(acc[2 * bg + 1], a0, a1, a2r, a3, b2, b3);
            }
        }
        if (t < 15) CP_WAIT0();
        __syncthreads();
    }

    // ---- row sums -> smem (reduce over 16 jq lanes sharing each row)
#pragma unroll
    for (int k = 0; k < 4; k++) {
        float s = rsum[k];
        s += __shfl_xor_sync(0xFFFFFFFFu, s, 1);
        s += __shfl_xor_sync(0xFFFFFFFFu, s, 2);
        s += __shfl_xor_sync(0xFFFFFFFFu, s, 4);
        s += __shfl_xor_sync(0xFFFFFFFFu, s, 8);
        if (jq == 0) sSum[rb + 8 * k] = s;
    }
    __syncthreads();

    // ---- epilogue: normalize + ELU + store
    {
        int rloc = 16 * mg + (lane >> 2);
        float s0 = sSum[rloc], s1 = sSum[rloc + 8];
        float inv0 = (s0 > 0.f) ? (1.f / s0) : 0.f;
        float inv1 = (s1 > 0.f) ? (1.f / s1) : 0.f;
        float* op0 = out + ((size_t)(bt * NN + i0 + rloc)) * 64;
        float* op1 = op0 + (size_t)8 * 64;
#pragma unroll
        for (int bg = 0; bg < 2; bg++)
#pragma unroll
            for (int h = 0; h < 2; h++) {
                int colb = 32 * ngrp + 16 * bg + 8 * h + (lane & 3) * 2;
                const float* A = acc[2 * bg + h];
                float v0 = A[0] * inv0, v1 = A[1] * inv0;
                float v2 = A[2] * inv1, v3 = A[3] * inv1;
                float2 o0, o1;
                o0.x = (v0 > 0.f) ? v0 : (__expf(v0) - 1.f);
                o0.y = (v1 > 0.f) ? v1 : (__expf(v1) - 1.f);
                o1.x = (v2 > 0.f) ? v2 : (__expf(v2) - 1.f);
                o1.y = (v3 > 0.f) ? v3 : (__expf(v3) - 1.f);
                *(float2*)(op0 + colb) = o0;
                *(float2*)(op1 + colb) = o1;
            }
    }
}

// ---------------------------------------------------------------- launch
extern "C" void kernel_launch(void* const* d_in, const int* in_sizes, int n_in,
                              void* d_out, int out_size) {
    const float* x = (const float*)d_in[0];
    const int* adj = (const int*)d_in[1];
    const float* emb1 = (const float*)d_in[2];
    const float* emb2 = (const float*)d_in[3];
    const float* W = (const float*)d_in[4];
    const float* a = (const float*)d_in[5];
    const float* a2 = (const float*)d_in[6];
    float* out = (float*)d_out;

    static int smem_set = 0;
    if (!smem_set) {
        cudaFuncSetAttribute(k_att, cudaFuncAttributeMaxDynamicSharedMemorySize, SMEM_DYN);
        smem_set = 1;
    }

    k_pack<<<1024, 256>>>(adj, W);
    dim3 gp(16, BT);
    k_prep<<<gp, 128>>>(x, a, emb1, emb2, a2);
    dim3 ga(32, BT);
    k_att<<<ga, 128, SMEM_DYN>>>(out);
}